// round 15
// baseline (speedup 1.0000x reference)
#include <cuda_runtime.h>
#include <math_constants.h>

// Problem constants
#define B_ 32
#define L_ 8192
#define C_ 256
#define S_ 32                 // L-splits
#define CHUNK_ (L_ / S_)      // 256
#define MLP_ 4
#define NROWS_ (B_ * C_)      // 8192

// Partials, two-plane layout, row = b*C + c, slot s in 0..31:
//   plane A: float4 {mn0, mn1, mn2, mx0}   (4 MB)
//   plane B: float2 {mx1, mx2}             (2 MB)
__device__ float4 g_partA[(size_t)NROWS_ * S_];
__device__ float2 g_partB[(size_t)NROWS_ * S_];
// Per-batch completion counters (zero-init; reset by reducer each run).
__device__ int g_cnt[B_];

// Merge running ascending triple with ascending (a0,a1,a2): keep 3 smallest. 7 ops.
__device__ __forceinline__ void merge_min(float a0, float a1, float a2,
                                          float& mn0, float& mn1, float& mn2) {
    float x0 = fminf(mn0, a0);
    float y0 = fmaxf(mn0, a0);
    float x1 = fminf(mn1, a1);
    float x2 = fminf(mn2, a2);
    float t  = fmaxf(x1, y0);
    mn0 = x0;
    mn1 = fminf(y0, x1);
    mn2 = fminf(x2, t);
}

// Merge running descending triple with descending (d0,d1,d2): keep 3 largest. 7 ops.
__device__ __forceinline__ void merge_max(float d0, float d1, float d2,
                                          float& mx0, float& mx1, float& mx2) {
    float x0 = fmaxf(mx0, d0);
    float y0 = fminf(mx0, d0);
    float x1 = fmaxf(mx1, d1);
    float x2 = fmaxf(mx2, d2);
    float t  = fminf(x1, y0);
    mx0 = x0;
    mx1 = fmaxf(y0, x1);
    mx2 = fmaxf(x2, t);
}

// Sort quad (10 ops) then merge both sides (7+7): 24 ops / 4 elements.
__device__ __forceinline__ void quad_update(float v0, float v1, float v2, float v3,
                                            float& mn0, float& mn1, float& mn2,
                                            float& mx0, float& mx1, float& mx2) {
    float a = fminf(v0, v1), b = fmaxf(v0, v1);
    float c = fminf(v2, v3), d = fmaxf(v2, v3);
    float a0 = fminf(a, c), t0 = fmaxf(a, c);
    float t1 = fminf(b, d), a3 = fmaxf(b, d);
    float a1 = fminf(t0, t1), a2 = fmaxf(t0, t1);
    merge_min(a0, a1, a2, mn0, mn1, mn2);   // a3 provably not among 3 smallest
    merge_max(a3, a2, a1, mx0, mx1, mx2);   // a0 provably not among 3 largest
}

// One launch, 1056 blocks x 256 threads:
//   blocks 0..1023  : workers — block (s = bid&31, b = bid>>5), exactly the
//                     proven pass-1 (MLP=4, __ldcs, branchless quad scan).
//   blocks 1024..1055: reducers — one per batch; resident from wave start,
//                     spin on g_cnt[b], then reduce that batch's 256 rows.
// Capacity: 8 blocks/SM x 148 SMs = 1184 >= 1056 -> all co-resident; workers
// cap at 7/SM (reducers fill the spare slots), preserving pass-1 geometry.
__global__ __launch_bounds__(256, 8) void kmm_onekernel(const float* __restrict__ x,
                                                        float* __restrict__ out) {
    const int bid = blockIdx.x;

    if (bid < S_ * B_) {
        // ---------------- worker ----------------
        const int c = threadIdx.x;
        const int s = bid & (S_ - 1);
        const int b = bid >> 5;

        const float* __restrict__ p =
            x + ((size_t)b * L_ + (size_t)s * CHUNK_) * C_ + c;

        float mx0 = -CUDART_INF_F, mx1 = -CUDART_INF_F, mx2 = -CUDART_INF_F;
        float mn0 =  CUDART_INF_F, mn1 =  CUDART_INF_F, mn2 =  CUDART_INF_F;

        for (int l = 0; l < CHUNK_; l += MLP_) {
            float v[MLP_];
#pragma unroll
            for (int j = 0; j < MLP_; j++)
                v[j] = __ldcs(p + (size_t)(l + j) * C_);
            quad_update(v[0], v[1], v[2], v[3], mn0, mn1, mn2, mx0, mx1, mx2);
        }

        const size_t slot = (size_t)(b * C_ + c) * S_ + s;
        g_partA[slot] = make_float4(mn0, mn1, mn2, mx0);
        g_partB[slot] = make_float2(mx1, mx2);

        // Release protocol: every thread fences its stores, THEN the block
        // synchronizes, THEN one thread increments the batch counter.
        __threadfence();
        __syncthreads();
        if (threadIdx.x == 0) atomicAdd(&g_cnt[b], 1);
        return;
    }

    // ---------------- reducer (one block per batch) ----------------
    const int b = bid - S_ * B_;

    if (threadIdx.x == 0) {
        while (atomicAdd(&g_cnt[b], 0) < S_) { /* spin */ }
    }
    __syncthreads();
    __threadfence();

    // 8 warps; per iteration a warp covers 2 rows (16 lanes/row, 2 slots/lane).
    const int lane = threadIdx.x & 31;
    const int w    = threadIdx.x >> 5;
    const int r    = lane >> 4;
    const int s0   = lane & 15;

    for (int iter = 0; iter < 16; iter++) {
        const int row = b * C_ + iter * 16 + w * 2 + r;
        const size_t base = (size_t)row * S_;

        float4 a0 = __ldcg(g_partA + base + s0);
        float4 a1 = __ldcg(g_partA + base + s0 + 16);
        float2 b0 = __ldcg(g_partB + base + s0);
        float2 b1 = __ldcg(g_partB + base + s0 + 16);

        float mn0 = a0.x, mn1 = a0.y, mn2 = a0.z;
        float mx0 = a0.w, mx1 = b0.x, mx2 = b0.y;
        merge_min(a1.x, a1.y, a1.z, mn0, mn1, mn2);
        merge_max(a1.w, b1.x, b1.y, mx0, mx1, mx2);

#pragma unroll
        for (int off = 8; off > 0; off >>= 1) {
            float q0 = __shfl_xor_sync(0xffffffffu, mn0, off);
            float q1 = __shfl_xor_sync(0xffffffffu, mn1, off);
            float q2 = __shfl_xor_sync(0xffffffffu, mn2, off);
            float w0 = __shfl_xor_sync(0xffffffffu, mx0, off);
            float w1 = __shfl_xor_sync(0xffffffffu, mx1, off);
            float w2 = __shfl_xor_sync(0xffffffffu, mx2, off);
            merge_min(q0, q1, q2, mn0, mn1, mn2);
            merge_max(w0, w1, w2, mx0, mx1, mx2);
        }

        if (s0 == 0) {
            float* rr = out + (size_t)row * 6;
            rr[0] = mn0; rr[1] = mn1; rr[2] = mn2;
            rr[3] = mx0; rr[4] = mx1; rr[5] = mx2;
        }
    }

    // Reset counter for the next graph replay.
    __syncthreads();
    if (threadIdx.x == 0) g_cnt[b] = 0;
}

extern "C" void kernel_launch(void* const* d_in, const int* in_sizes, int n_in,
                              void* d_out, int out_size) {
    const float* x = (const float*)d_in[0];
    float* out = (float*)d_out;

    kmm_onekernel<<<S_ * B_ + B_, 256>>>(x, out);
}

// round 16
// speedup vs baseline: 1.0848x; 1.0848x over previous
#include <cuda_runtime.h>
#include <math_constants.h>

// Problem constants
#define B_ 32
#define L_ 8192
#define C_ 256
#define S_ 32                 // L-splits (== blocks per batch)
#define CHUNK_ (L_ / S_)      // 256
#define MLP_ 4
#define NROWS_ (B_ * C_)      // 8192
#define RED0_ 24              // blocks with s >= RED0_ also reduce
#define NRED_ (S_ - RED0_)    // 8 reducer blocks per batch

// Partials, two-plane layout, row = b*C + c, slot s in 0..31:
//   plane A: float4 {mn0, mn1, mn2, mx0}   (4 MB)
//   plane B: float2 {mx1, mx2}             (2 MB)
__device__ float4 g_partA[(size_t)NROWS_ * S_];
__device__ float2 g_partB[(size_t)NROWS_ * S_];
// Per-batch counters (zero-init; self-resetting each run).
__device__ int g_cnt[B_];

// Merge running ascending triple with ascending (a0,a1,a2): keep 3 smallest. 7 ops.
__device__ __forceinline__ void merge_min(float a0, float a1, float a2,
                                          float& mn0, float& mn1, float& mn2) {
    float x0 = fminf(mn0, a0);
    float y0 = fmaxf(mn0, a0);
    float x1 = fminf(mn1, a1);
    float x2 = fminf(mn2, a2);
    float t  = fmaxf(x1, y0);
    mn0 = x0;
    mn1 = fminf(y0, x1);
    mn2 = fminf(x2, t);
}

// Merge running descending triple with descending (d0,d1,d2): keep 3 largest. 7 ops.
__device__ __forceinline__ void merge_max(float d0, float d1, float d2,
                                          float& mx0, float& mx1, float& mx2) {
    float x0 = fmaxf(mx0, d0);
    float y0 = fminf(mx0, d0);
    float x1 = fmaxf(mx1, d1);
    float x2 = fmaxf(mx2, d2);
    float t  = fminf(x1, y0);
    mx0 = x0;
    mx1 = fmaxf(y0, x1);
    mx2 = fmaxf(x2, t);
}

// Sort quad (10 ops) then merge both sides (7+7): 24 ops / 4 elements.
__device__ __forceinline__ void quad_update(float v0, float v1, float v2, float v3,
                                            float& mn0, float& mn1, float& mn2,
                                            float& mx0, float& mx1, float& mx2) {
    float a = fminf(v0, v1), b = fmaxf(v0, v1);
    float c = fminf(v2, v3), d = fmaxf(v2, v3);
    float a0 = fminf(a, c), t0 = fmaxf(a, c);
    float t1 = fminf(b, d), a3 = fmaxf(b, d);
    float a1 = fminf(t0, t1), a2 = fmaxf(t0, t1);
    merge_min(a0, a1, a2, mn0, mn1, mn2);   // a3 provably not among 3 smallest
    merge_max(a3, a2, a1, mx0, mx1, mx2);   // a0 provably not among 3 largest
}

// Single launch, grid (S, B) = 1024 blocks x 256 threads — the proven R10
// geometry (8 blocks/SM cap, max 7/SM, balance 1.01). EVERY block is a
// worker; blocks with s >= 24 additionally reduce 32 rows of their batch
// once all 32 sibling blocks have released.
__global__ __launch_bounds__(256, 8) void kmm_onepass(const float* __restrict__ x,
                                                      float* __restrict__ out) {
    const int s = blockIdx.x;
    const int b = blockIdx.y;
    const int c = threadIdx.x;

    // ---------------- worker scan (all 1024 blocks) ----------------
    {
        const float* __restrict__ p =
            x + ((size_t)b * L_ + (size_t)s * CHUNK_) * C_ + c;

        float mx0 = -CUDART_INF_F, mx1 = -CUDART_INF_F, mx2 = -CUDART_INF_F;
        float mn0 =  CUDART_INF_F, mn1 =  CUDART_INF_F, mn2 =  CUDART_INF_F;

        for (int l = 0; l < CHUNK_; l += MLP_) {
            float v[MLP_];
#pragma unroll
            for (int j = 0; j < MLP_; j++)
                v[j] = __ldcs(p + (size_t)(l + j) * C_);
            quad_update(v[0], v[1], v[2], v[3], mn0, mn1, mn2, mx0, mx1, mx2);
        }

        const size_t slot = (size_t)(b * C_ + c) * S_ + s;
        g_partA[slot] = make_float4(mn0, mn1, mn2, mx0);
        g_partB[slot] = make_float2(mx1, mx2);
    }

    // Release: fence stores, block-sync, then one counter increment.
    __threadfence();
    __syncthreads();
    if (threadIdx.x == 0) atomicAdd(&g_cnt[b], 1);

    if (s < RED0_) return;

    // ---------------- reducer (8 blocks per batch, 32 rows each) ----------------
    if (threadIdx.x == 0) {
        while (atomicAdd(&g_cnt[b], 0) < S_) { /* spin */ }
    }
    __syncthreads();
    __threadfence();   // acquire: order partial reads after observed release

    // R11 scheme: 2 rows/warp, 16 lanes/row, 2 slots/lane; 16 rows per pass,
    // 2 passes -> 32 rows per reducer block.
    const int lane = threadIdx.x & 31;
    const int w    = threadIdx.x >> 5;
    const int r    = lane >> 4;
    const int s0   = lane & 15;
    const int rowbase = b * C_ + (s - RED0_) * 32;

#pragma unroll
    for (int iter = 0; iter < 2; iter++) {
        const int row = rowbase + iter * 16 + w * 2 + r;
        const size_t base = (size_t)row * S_;

        float4 a0 = __ldcg(g_partA + base + s0);
        float4 a1 = __ldcg(g_partA + base + s0 + 16);
        float2 b0 = __ldcg(g_partB + base + s0);
        float2 b1 = __ldcg(g_partB + base + s0 + 16);

        float mn0 = a0.x, mn1 = a0.y, mn2 = a0.z;
        float mx0 = a0.w, mx1 = b0.x, mx2 = b0.y;
        merge_min(a1.x, a1.y, a1.z, mn0, mn1, mn2);
        merge_max(a1.w, b1.x, b1.y, mx0, mx1, mx2);

#pragma unroll
        for (int off = 8; off > 0; off >>= 1) {
            float q0 = __shfl_xor_sync(0xffffffffu, mn0, off);
            float q1 = __shfl_xor_sync(0xffffffffu, mn1, off);
            float q2 = __shfl_xor_sync(0xffffffffu, mn2, off);
            float w0 = __shfl_xor_sync(0xffffffffu, mx0, off);
            float w1 = __shfl_xor_sync(0xffffffffu, mx1, off);
            float w2 = __shfl_xor_sync(0xffffffffu, mx2, off);
            merge_min(q0, q1, q2, mn0, mn1, mn2);
            merge_max(w0, w1, w2, mx0, mx1, mx2);
        }

        if (s0 == 0) {
            float* rr = out + (size_t)row * 6;
            rr[0] = mn0; rr[1] = mn1; rr[2] = mn2;
            rr[3] = mx0; rr[4] = mx1; rr[5] = mx2;
        }
    }

    // Reset phase: each reducer adds again (counter runs 33..40); the last
    // one (old == 39) resets to 0 for the next graph replay. All reads of
    // g_cnt[b] in this run happen before these adds, so the reset is safe.
    __syncthreads();
    if (threadIdx.x == 0) {
        int old = atomicAdd(&g_cnt[b], 1);
        if (old == S_ + NRED_ - 1) atomicExch(&g_cnt[b], 0);
    }
}

extern "C" void kernel_launch(void* const* d_in, const int* in_sizes, int n_in,
                              void* d_out, int out_size) {
    const float* x = (const float*)d_in[0];
    float* out = (float*)d_out;

    dim3 grid(S_, B_);   // (32, 32) = 1024 blocks
    kmm_onepass<<<grid, 256>>>(x, out);
}